// round 5
// baseline (speedup 1.0000x reference)
#include <cuda_runtime.h>
#include <cuda_fp16.h>
#include <math.h>
#include <stdint.h>

#define BATCH 2
#define SEQ   4096
#define DIM   128
#define NTOK  (BATCH * SEQ)
#define SCALE 0.125f   // 64^-0.5

// ---------------- device scratch ----------------
__device__ float  g_W[640 * 128];
__device__ float  g_q[NTOK * DIM];            // reused as h1 after flash
__device__ float  g_k2[NTOK * DIM * 2];       // [tok][d][hi,lo]
__device__ float  g_vT2[(size_t)DIM * NTOK * 2]; // [d][tok][hi,lo]
__device__ float  g_sq[NTOK];
__device__ __half g_dist[(size_t)BATCH * SEQ * SEQ]; // dist, then combined mask (in-place)
__device__ double g_sum_spe;
__device__ float  g_inv2s2_spe;
__device__ float  g_spa[64 * 64];
__device__ float  g_attn[NTOK * DIM];

// ---------------- tf32 helpers ----------------
__device__ __forceinline__ uint32_t f2tf(float f) {
    uint32_t r; asm("cvt.rna.tf32.f32 %0, %1;" : "=r"(r) : "f"(f)); return r;
}
__device__ __forceinline__ void split_tf(float f, uint32_t& hi, uint32_t& lo) {
    hi = f2tf(f);
    lo = f2tf(f - __uint_as_float(hi));
}
__device__ __forceinline__ void mma8(float* c, const uint32_t* a, uint32_t b0, uint32_t b1) {
    asm volatile("mma.sync.aligned.m16n8k8.row.col.f32.tf32.tf32.f32 "
                 "{%0,%1,%2,%3},{%4,%5,%6,%7},{%8,%9},{%0,%1,%2,%3};"
                 : "+f"(c[0]), "+f"(c[1]), "+f"(c[2]), "+f"(c[3])
                 : "r"(a[0]), "r"(a[1]), "r"(a[2]), "r"(a[3]), "r"(b0), "r"(b1));
}

// ---------------- init ----------------
__global__ void k_init() { g_sum_spe = 0.0; }

// ---------------- weight norm ----------------
__global__ void k_weights(const float* __restrict__ vq, const float* __restrict__ gq,
                          const float* __restrict__ v1, const float* __restrict__ g1,
                          const float* __restrict__ v2, const float* __restrict__ g2) {
    int r = blockIdx.x, t = threadIdx.x;
    const float* v; float g;
    if (r < 384)      { v = vq + r * 128;        g = gq[r]; }
    else if (r < 512) { v = v1 + (r - 384) * 128; g = g1[r - 384]; }
    else              { v = v2 + (r - 512) * 128; g = g2[r - 512]; }
    float val = v[t];
    float ss = val * val;
    #pragma unroll
    for (int o = 16; o; o >>= 1) ss += __shfl_xor_sync(0xffffffffu, ss, o);
    __shared__ float ws[4];
    if ((t & 31) == 0) ws[t >> 5] = ss;
    __syncthreads();
    float tot = ws[0] + ws[1] + ws[2] + ws[3];
    g_W[r * 128 + t] = val * (g / sqrtf(tot));
}

// ---------------- per-token ||x||^2 ----------------
__global__ void k_sq(const float* __restrict__ x) {
    int token = blockIdx.x * 8 + (threadIdx.x >> 5);
    int lane  = threadIdx.x & 31;
    const float4* xp = (const float4*)(x + token * 128);
    float4 a = xp[lane];
    float ss = a.x * a.x + a.y * a.y + a.z * a.z + a.w * a.w;
    #pragma unroll
    for (int o = 16; o; o >>= 1) ss += __shfl_xor_sync(0xffffffffu, ss, o);
    if (lane == 0) g_sq[token] = ss;
}

// ---------------- tiled projection GEMM (scalar fp32, exact) ----------------
// mode 0: q plain, k/v split hi/lo (v transposed); mode 1: GELU -> g_q; mode 2: plain -> out
__global__ void __launch_bounds__(256) k_gemm64(const float* __restrict__ A,
                                                const float* __restrict__ Wrows,
                                                const float* __restrict__ bias,
                                                float* __restrict__ out, int mode) {
    extern __shared__ float sm[];
    float* aT = sm;
    float* wT = sm + 128 * 68;
    int c0 = blockIdx.x * 64;
    int t0 = blockIdx.y * 64;
    int tid = threadIdx.x;
    for (int idx = tid; idx < 64 * 128; idx += 256) {
        int r = idx >> 7, k = idx & 127;
        aT[k * 68 + r] = A[(t0 + r) * 128 + k];
        wT[k * 68 + r] = Wrows[(c0 + r) * 128 + k];
    }
    __syncthreads();
    int ty = tid >> 4, tx = tid & 15;
    float acc[4][4] = {};
    #pragma unroll 4
    for (int k = 0; k < 128; k++) {
        float4 av = *(const float4*)&aT[k * 68 + 4 * ty];
        float4 bv = *(const float4*)&wT[k * 68 + 4 * tx];
        float a[4] = {av.x, av.y, av.z, av.w};
        float c[4] = {bv.x, bv.y, bv.z, bv.w};
        #pragma unroll
        for (int i = 0; i < 4; i++)
            #pragma unroll
            for (int j = 0; j < 4; j++) acc[i][j] = fmaf(a[i], c[j], acc[i][j]);
    }
    #pragma unroll
    for (int i = 0; i < 4; i++) {
        int token = t0 + 4 * ty + i;
        #pragma unroll
        for (int j = 0; j < 4; j++) {
            int c = c0 + 4 * tx + j;
            float val = acc[i][j] + __ldg(&bias[c]);
            if (mode == 0) {
                if (c < 128) {
                    g_q[token * 128 + c] = val;
                } else if (c < 256) {
                    uint32_t hi, lo; split_tf(val, hi, lo);
                    float2 p = {__uint_as_float(hi), __uint_as_float(lo)};
                    *(float2*)&g_k2[((size_t)token * 128 + (c - 128)) * 2] = p;
                } else {
                    uint32_t hi, lo; split_tf(val, hi, lo);
                    float2 p = {__uint_as_float(hi), __uint_as_float(lo)};
                    *(float2*)&g_vT2[((size_t)(c - 256) * NTOK + token) * 2] = p;
                }
            } else if (mode == 1) {
                g_q[token * 128 + c] = 0.5f * val * (1.0f + erff(val * 0.70710678118654752f));
            } else {
                out[token * 128 + c] = val;
            }
        }
    }
}

// ---------------- pairwise distance via tf32 MMA (tf32 pre-converted at fill) ----------------
__global__ void __launch_bounds__(256) k_dist(const float* __restrict__ x) {
    extern __shared__ float sm[];
    float* xi = sm;              // [128][132], tf32-rounded
    float* xj = sm + 128 * 132;
    int b = blockIdx.z, i0 = blockIdx.y * 128, j0 = blockIdx.x * 128;
    int tid = threadIdx.x;
    for (int fi = tid; fi < 4096; fi += 256) {
        int r = fi >> 5, c4 = (fi & 31) * 4;
        float4 a = *(const float4*)&x[(size_t)(b * SEQ + i0 + r) * 128 + c4];
        float4 bb = *(const float4*)&x[(size_t)(b * SEQ + j0 + r) * 128 + c4];
        a.x = __uint_as_float(f2tf(a.x)); a.y = __uint_as_float(f2tf(a.y));
        a.z = __uint_as_float(f2tf(a.z)); a.w = __uint_as_float(f2tf(a.w));
        bb.x = __uint_as_float(f2tf(bb.x)); bb.y = __uint_as_float(f2tf(bb.y));
        bb.z = __uint_as_float(f2tf(bb.z)); bb.w = __uint_as_float(f2tf(bb.w));
        *(float4*)&xi[r * 132 + c4] = a;
        *(float4*)&xj[r * 132 + c4] = bb;
    }
    __syncthreads();
    int lane = tid & 31, w = tid >> 5;
    int wr = w >> 1, wc = w & 1;
    int g = lane >> 2, t = lane & 3;
    float c[2][8][4] = {};
    #pragma unroll 1
    for (int ks = 0; ks < 16; ks++) {
        uint32_t A[2][4];
        #pragma unroll
        for (int mt = 0; mt < 2; mt++)
            #pragma unroll
            for (int e = 0; e < 4; e++)
                A[mt][e] = __float_as_uint(xi[(32 * wr + 16 * mt + g + 8 * (e & 1)) * 132 + 8 * ks + t + 4 * (e >> 1)]);
        #pragma unroll
        for (int nt = 0; nt < 8; nt++) {
            int row = (64 * wc + 8 * nt + g) * 132 + 8 * ks + t;
            uint32_t b0 = __float_as_uint(xj[row]);
            uint32_t b1 = __float_as_uint(xj[row + 4]);
            mma8(c[0][nt], A[0], b0, b1);
            mma8(c[1][nt], A[1], b0, b1);
        }
    }
    float lsum = 0.f;
    #pragma unroll
    for (int mt = 0; mt < 2; mt++) {
        int ir0 = i0 + 32 * wr + 16 * mt + g;
        float sqi0 = __ldg(&g_sq[b * SEQ + ir0]);
        float sqi1 = __ldg(&g_sq[b * SEQ + ir0 + 8]);
        #pragma unroll
        for (int nt = 0; nt < 8; nt++) {
            int jc = j0 + 64 * wc + 8 * nt + 2 * t;
            float sj0 = __ldg(&g_sq[b * SEQ + jc]);
            float sj1 = __ldg(&g_sq[b * SEQ + jc + 1]);
            float d00 = sqrtf(fmaxf(sqi0 + sj0 - 2.f * c[mt][nt][0], 0.f));
            float d01 = sqrtf(fmaxf(sqi0 + sj1 - 2.f * c[mt][nt][1], 0.f));
            float d10 = sqrtf(fmaxf(sqi1 + sj0 - 2.f * c[mt][nt][2], 0.f));
            float d11 = sqrtf(fmaxf(sqi1 + sj1 - 2.f * c[mt][nt][3], 0.f));
            lsum += d00 + d01 + d10 + d11;
            *(__half2*)&g_dist[(size_t)(b * SEQ + ir0) * SEQ + jc]     = __floats2half2_rn(d00, d01);
            *(__half2*)&g_dist[(size_t)(b * SEQ + ir0 + 8) * SEQ + jc] = __floats2half2_rn(d10, d11);
        }
    }
    #pragma unroll
    for (int o = 16; o; o >>= 1) lsum += __shfl_xor_sync(0xffffffffu, lsum, o);
    __shared__ float rsum[8];
    if (lane == 0) rsum[w] = lsum;
    __syncthreads();
    if (tid == 0) {
        float tot = 0.f;
        #pragma unroll
        for (int i = 0; i < 8; i++) tot += rsum[i];
        atomicAdd(&g_sum_spe, (double)tot);
    }
}

// ---------------- finalize sigmas + spatial LUT ----------------
__global__ void k_finalize() {
    int t = threadIdx.x;
    __shared__ double red[256];
    double local = 0.0;
    for (int idx = t; idx < 64 * 64; idx += 256) {
        int adx = idx >> 6, ady = idx & 63;
        double cx = adx ? 2.0 * (64 - adx) : 64.0;
        double cy = ady ? 2.0 * (64 - ady) : 64.0;
        local += cx * cy * sqrt((double)(adx * adx + ady * ady));
    }
    red[t] = local; __syncthreads();
    for (int s = 128; s; s >>= 1) { if (t < s) red[t] += red[t + s]; __syncthreads(); }
    __shared__ float inv_spa;
    if (t == 0) {
        double sig_spa = red[0] / ((double)SEQ * (double)SEQ);
        inv_spa = (float)(1.0 / (2.0 * sig_spa * sig_spa));
        double sig_spe = g_sum_spe / ((double)BATCH * (double)SEQ * (double)SEQ);
        g_inv2s2_spe = (float)(1.0 / (2.0 * sig_spe * sig_spe));
    }
    __syncthreads();
    float iv = inv_spa;
    for (int idx = t; idx < 64 * 64; idx += 256) {
        int adx = idx >> 6, ady = idx & 63;
        g_spa[idx] = expf(-sqrtf((float)(adx * adx + ady * ady)) * iv);
    }
}

// ---------------- mask transform: dist -> spa * exp(-dist/(2s^2)) in place (fp16) ----------------
__global__ void k_mask() {
    float inv_spe = g_inv2s2_spe;
    size_t e = (size_t)blockIdx.x * blockDim.x + threadIdx.x;   // half2 index
    const size_t total = (size_t)BATCH * SEQ * SEQ / 2;
    size_t stride = (size_t)gridDim.x * blockDim.x;
    for (; e < total; e += stride) {
        int i = (int)((e >> 11) & 4095);
        int j = (int)((e & 2047) << 1);
        __half2 d2 = *(__half2*)&g_dist[e * 2];
        float2 df = __half22float2(d2);
        int gxi = i >> 6, gyi = i & 63;
        int adx0 = abs(gxi - (j >> 6)),       ady0 = abs(gyi - (j & 63));
        int adx1 = abs(gxi - ((j + 1) >> 6)), ady1 = abs(gyi - ((j + 1) & 63));
        float w0 = __ldg(&g_spa[adx0 * 64 + ady0]) * __expf(-df.x * inv_spe);
        float w1 = __ldg(&g_spa[adx1 * 64 + ady1]) * __expf(-df.y * inv_spe);
        *(__half2*)&g_dist[e * 2] = __floats2half2_rn(w0, w1);
    }
}

// ---------------- flash attention, 3xTF32, interleaved hi/lo smem ----------------
// smem (float2 units): K [64][132] @0, V [128][68] @8448, P [2][64][68] @17152; total 206848 B
#define FLASH_SMEM_BYTES (25856 * 8)
__global__ void __launch_bounds__(256, 1) k_flash() {
    extern __shared__ float2 sf[];
    float2* smK = sf;            // [tok 64][d 128 +pad4]
    float2* smV = sf + 8448;     // [d 128][j 64 +pad4]
    float2* smP = sf + 17152;    // [h*64+row][col 64 +pad4]
    int b  = blockIdx.y;
    int i0 = blockIdx.x * 64;
    int tid = threadIdx.x;
    int lane = tid & 31, w = tid >> 5;
    int h = w >> 2, ms = w & 3;
    int g = lane >> 2, t = lane & 3;
    int hb = h * 64;
    int r0loc = 16 * ms + g;

    // Q fragments hi/lo (registers, reused across jtiles)
    uint32_t qh[8][4], ql[8][4];
    #pragma unroll
    for (int ks = 0; ks < 8; ks++)
        #pragma unroll
        for (int e = 0; e < 4; e++) {
            int row = i0 + 16 * ms + g + (e & 1) * 8;
            int col = hb + ks * 8 + t + (e >> 1) * 4;
            split_tf(g_q[(size_t)(b * SEQ + row) * 128 + col], qh[ks][e], ql[ks][e]);
        }

    float co[8][4] = {};
    float m0 = -1e30f, m1 = -1e30f, l0 = 0.f, l1 = 0.f;
    float2* myP = smP + (hb) * 68;

    for (int jt = 0; jt < 64; jt++) {
        int j0 = jt * 64;
        __syncthreads();
        // fill K: straight copy of pre-split rows
        #pragma unroll
        for (int fi = tid; fi < 4096; fi += 256) {
            int r = fi >> 6, c4 = fi & 63;   // c4 indexes float4 (2 dims)
            float4 v = *(const float4*)&g_k2[((size_t)(b * SEQ + j0 + r) * 128 + 2 * c4) * 2];
            *(float4*)&smK[r * 132 + 2 * c4] = v;
        }
        // fill V: straight copy of pre-split transposed rows
        #pragma unroll
        for (int fi = tid; fi < 4096; fi += 256) {
            int d = fi >> 5, j4 = (fi & 31) * 2;  // 2 tokens per float4
            float4 v = *(const float4*)&g_vT2[((size_t)d * NTOK + b * SEQ + j0 + j4) * 2];
            *(float4*)&smV[d * 68 + j4] = v;
        }
        __syncthreads();

        // --- QK^T 3xTF32 ---
        float cs[8][4] = {};
        #pragma unroll
        for (int ks = 0; ks < 8; ks++) {
            #pragma unroll
            for (int nt = 0; nt < 8; nt++) {
                const float2* kr = &smK[(8 * nt + g) * 132 + hb + 8 * ks + t];
                float2 e0 = kr[0];
                float2 e1 = kr[4];
                uint32_t h0 = __float_as_uint(e0.x), h1 = __float_as_uint(e1.x);
                uint32_t lo0 = __float_as_uint(e0.y), lo1 = __float_as_uint(e1.y);
                mma8(cs[nt], qh[ks], h0, h1);
                mma8(cs[nt], qh[ks], lo0, lo1);
                mma8(cs[nt], ql[ks], h0, h1);
            }
        }

        // --- mask (precombined, direct gmem) + online softmax ---
        float mloc0 = -1e30f, mloc1 = -1e30f;
        size_t mrow0 = ((size_t)(b * SEQ + i0 + r0loc)) * SEQ + j0;
        size_t mrow1 = mrow0 + 8 * (size_t)SEQ;
        #pragma unroll
        for (int nt = 0; nt < 8; nt++) {
            int col = 8 * nt + 2 * t;
            float2 wa = __half22float2(*(const __half2*)&g_dist[mrow0 + col]);
            float2 wb = __half22float2(*(const __half2*)&g_dist[mrow1 + col]);
            cs[nt][0] *= SCALE * wa.x; cs[nt][1] *= SCALE * wa.y;
            cs[nt][2] *= SCALE * wb.x; cs[nt][3] *= SCALE * wb.y;
            mloc0 = fmaxf(mloc0, fmaxf(cs[nt][0], cs[nt][1]));
            mloc1 = fmaxf(mloc1, fmaxf(cs[nt][2], cs[nt][3]));
        }
        #pragma unroll
        for (int o = 1; o <= 2; o <<= 1) {
            mloc0 = fmaxf(mloc0, __shfl_xor_sync(0xffffffffu, mloc0, o));
            mloc1 = fmaxf(mloc1, __shfl_xor_sync(0xffffffffu, mloc1, o));
        }
        float mn0 = fmaxf(m0, mloc0), mn1 = fmaxf(m1, mloc1);
        float corr0 = __expf(m0 - mn0), corr1 = __expf(m1 - mn1);
        m0 = mn0; m1 = mn1;
        float rs0 = 0.f, rs1 = 0.f;
        #pragma unroll
        for (int nt = 0; nt < 8; nt++) {
            float p0 = __expf(cs[nt][0] - mn0), p1 = __expf(cs[nt][1] - mn0);
            float p2 = __expf(cs[nt][2] - mn1), p3 = __expf(cs[nt][3] - mn1);
            rs0 += p0 + p1; rs1 += p2 + p3;
            int col = 8 * nt + 2 * t;
            uint32_t a0, a1, b0_, b1_;
            split_tf(p0, a0, a1); split_tf(p1, b0_, b1_);
            float4 st = {__uint_as_float(a0), __uint_as_float(a1),
                         __uint_as_float(b0_), __uint_as_float(b1_)};
            *(float4*)&myP[r0loc * 68 + col] = st;
            split_tf(p2, a0, a1); split_tf(p3, b0_, b1_);
            float4 st2 = {__uint_as_float(a0), __uint_as_float(a1),
                          __uint_as_float(b0_), __uint_as_float(b1_)};
            *(float4*)&myP[(r0loc + 8) * 68 + col] = st2;
        }
        #pragma unroll
        for (int o = 1; o <= 2; o <<= 1) {
            rs0 += __shfl_xor_sync(0xffffffffu, rs0, o);
            rs1 += __shfl_xor_sync(0xffffffffu, rs1, o);
        }
        l0 = l0 * corr0 + rs0;
        l1 = l1 * corr1 + rs1;
        #pragma unroll
        for (int nt = 0; nt < 8; nt++) {
            co[nt][0] *= corr0; co[nt][1] *= corr0;
            co[nt][2] *= corr1; co[nt][3] *= corr1;
        }
        __syncwarp();

        // --- PV 3xTF32 ---
        #pragma unroll
        for (int ks = 0; ks < 8; ks++) {
            const float2* pr = &myP[r0loc * 68 + 8 * ks + t];
            float2 f0 = pr[0];
            float2 f1 = pr[8 * 68];
            float2 f2 = pr[4];
            float2 f3 = pr[8 * 68 + 4];
            uint32_t ah[4] = {__float_as_uint(f0.x), __float_as_uint(f1.x),
                              __float_as_uint(f2.x), __float_as_uint(f3.x)};
            uint32_t al[4] = {__float_as_uint(f0.y), __float_as_uint(f1.y),
                              __float_as_uint(f2.y), __float_as_uint(f3.y)};
            #pragma unroll
            for (int nt = 0; nt < 8; nt++) {
                const float2* vr = &smV[(hb + 8 * nt + g) * 68 + 8 * ks + t];
                float2 e0 = vr[0];
                float2 e1 = vr[4];
                uint32_t h0 = __float_as_uint(e0.x), h1 = __float_as_uint(e1.x);
                uint32_t lo0 = __float_as_uint(e0.y), lo1 = __float_as_uint(e1.y);
                mma8(co[nt], ah, h0, h1);
                mma8(co[nt], ah, lo0, lo1);
                mma8(co[nt], al, h0, h1);
            }
        }
    }

    // --- epilogue ---
    float li0 = 1.f / l0, li1 = 1.f / l1;
    #pragma unroll
    for (int nt = 0; nt < 8; nt++) {
        int col = hb + 8 * nt + 2 * t;
        int row0 = b * SEQ + i0 + r0loc;
        float2 o0 = {co[nt][0] * li0, co[nt][1] * li0};
        float2 o1 = {co[nt][2] * li1, co[nt][3] * li1};
        *(float2*)&g_attn[(size_t)row0 * 128 + col] = o0;
        *(float2*)&g_attn[(size_t)(row0 + 8) * 128 + col] = o1;
    }
}

// ---------------- launch ----------------
extern "C" void kernel_launch(void* const* d_in, const int* in_sizes, int n_in,
                              void* d_out, int out_size) {
    const float* x      = (const float*)d_in[0];
    const float* v_qkv  = (const float*)d_in[1];
    const float* g_qkv_ = (const float*)d_in[2];
    const float* b_qkv  = (const float*)d_in[3];
    const float* v_ff1  = (const float*)d_in[4];
    const float* g_ff1  = (const float*)d_in[5];
    const float* b_ff1  = (const float*)d_in[6];
    const float* v_ff2  = (const float*)d_in[7];
    const float* g_ff2  = (const float*)d_in[8];
    const float* b_ff2  = (const float*)d_in[9];
    float* out = (float*)d_out;

    const int GEMM_SMEM  = 2 * 128 * 68 * 4;
    const int DIST_SMEM  = 2 * 128 * 132 * 4;
    cudaFuncSetAttribute(k_gemm64, cudaFuncAttributeMaxDynamicSharedMemorySize, GEMM_SMEM);
    cudaFuncSetAttribute(k_dist,   cudaFuncAttributeMaxDynamicSharedMemorySize, DIST_SMEM);
    cudaFuncSetAttribute(k_flash,  cudaFuncAttributeMaxDynamicSharedMemorySize, FLASH_SMEM_BYTES);

    float* Wdev = nullptr;     cudaGetSymbolAddress((void**)&Wdev, g_W);
    float* attn_dev = nullptr; cudaGetSymbolAddress((void**)&attn_dev, g_attn);
    float* h1_dev = nullptr;   cudaGetSymbolAddress((void**)&h1_dev, g_q);

    k_init<<<1, 1>>>();
    k_weights<<<640, 128>>>(v_qkv, g_qkv_, v_ff1, g_ff1, v_ff2, g_ff2);
    k_sq<<<NTOK / 8, 256>>>(x);
    k_gemm64<<<dim3(6, NTOK / 64), 256, GEMM_SMEM>>>(x, Wdev, b_qkv, nullptr, 0);
    k_dist<<<dim3(32, 32, BATCH), 256, DIST_SMEM>>>(x);
    k_finalize<<<1, 256>>>();
    k_mask<<<8192, 256>>>();
    k_flash<<<dim3(64, BATCH), 256, FLASH_SMEM_BYTES>>>();
    k_gemm64<<<dim3(2, NTOK / 64), 256, GEMM_SMEM>>>(attn_dev, Wdev + 384 * 128, b_ff1, nullptr, 1);
    k_gemm64<<<dim3(2, NTOK / 64), 256, GEMM_SMEM>>>(h1_dev, Wdev + 512 * 128, b_ff2, out, 2);
}

// round 6
// speedup vs baseline: 1.9754x; 1.9754x over previous
#include <cuda_runtime.h>
#include <cuda_fp16.h>
#include <math.h>
#include <stdint.h>

#define BATCH 2
#define SEQ   4096
#define DIM   128
#define NTOK  (BATCH * SEQ)
#define SCALE 0.125f   // 64^-0.5

// ---------------- device scratch ----------------
__device__ float  g_W[640 * 128];
__device__ float  g_q[NTOK * DIM];            // reused as h1 after flash
__device__ __half g_kh[NTOK * DIM];           // K hi plane [tok][d]
__device__ __half g_kl[NTOK * DIM];           // K lo plane
__device__ __half g_vh[(size_t)DIM * NTOK];   // V fp16, transposed [d][tok]
__device__ float  g_sq[NTOK];
__device__ __half g_dist[(size_t)BATCH * SEQ * SEQ]; // fp16 distances
__device__ double g_sum_spe;
__device__ float  g_inv2s2_spe;
__device__ float  g_spa[64 * 64];
__device__ float  g_attn[NTOK * DIM];

// ---------------- helpers ----------------
__device__ __forceinline__ uint32_t f2tf(float f) {
    uint32_t r; asm("cvt.rna.tf32.f32 %0, %1;" : "=r"(r) : "f"(f)); return r;
}
__device__ __forceinline__ void mma8(float* c, const uint32_t* a, uint32_t b0, uint32_t b1) {
    asm volatile("mma.sync.aligned.m16n8k8.row.col.f32.tf32.tf32.f32 "
                 "{%0,%1,%2,%3},{%4,%5,%6,%7},{%8,%9},{%0,%1,%2,%3};"
                 : "+f"(c[0]), "+f"(c[1]), "+f"(c[2]), "+f"(c[3])
                 : "r"(a[0]), "r"(a[1]), "r"(a[2]), "r"(a[3]), "r"(b0), "r"(b1));
}
__device__ __forceinline__ void mma16(float* c, const uint32_t* a, uint32_t b0, uint32_t b1) {
    asm volatile("mma.sync.aligned.m16n8k16.row.col.f32.f16.f16.f32 "
                 "{%0,%1,%2,%3},{%4,%5,%6,%7},{%8,%9},{%0,%1,%2,%3};"
                 : "+f"(c[0]), "+f"(c[1]), "+f"(c[2]), "+f"(c[3])
                 : "r"(a[0]), "r"(a[1]), "r"(a[2]), "r"(a[3]), "r"(b0), "r"(b1));
}

// ---------------- init ----------------
__global__ void k_init() { g_sum_spe = 0.0; }

// ---------------- weight norm ----------------
__global__ void k_weights(const float* __restrict__ vq, const float* __restrict__ gq,
                          const float* __restrict__ v1, const float* __restrict__ g1,
                          const float* __restrict__ v2, const float* __restrict__ g2) {
    int r = blockIdx.x, t = threadIdx.x;
    const float* v; float g;
    if (r < 384)      { v = vq + r * 128;        g = gq[r]; }
    else if (r < 512) { v = v1 + (r - 384) * 128; g = g1[r - 384]; }
    else              { v = v2 + (r - 512) * 128; g = g2[r - 512]; }
    float val = v[t];
    float ss = val * val;
    #pragma unroll
    for (int o = 16; o; o >>= 1) ss += __shfl_xor_sync(0xffffffffu, ss, o);
    __shared__ float ws[4];
    if ((t & 31) == 0) ws[t >> 5] = ss;
    __syncthreads();
    float tot = ws[0] + ws[1] + ws[2] + ws[3];
    g_W[r * 128 + t] = val * (g / sqrtf(tot));
}

// ---------------- per-token ||x||^2 ----------------
__global__ void k_sq(const float* __restrict__ x) {
    int token = blockIdx.x * 8 + (threadIdx.x >> 5);
    int lane  = threadIdx.x & 31;
    const float4* xp = (const float4*)(x + token * 128);
    float4 a = xp[lane];
    float ss = a.x * a.x + a.y * a.y + a.z * a.z + a.w * a.w;
    #pragma unroll
    for (int o = 16; o; o >>= 1) ss += __shfl_xor_sync(0xffffffffu, ss, o);
    if (lane == 0) g_sq[token] = ss;
}

// ---------------- tiled projection GEMM (scalar fp32, exact) ----------------
// mode 0: q fp32, k fp16 hi/lo planes, v fp16 transposed; mode 1: GELU->g_q; mode 2: ->out
__global__ void __launch_bounds__(256) k_gemm64(const float* __restrict__ A,
                                                const float* __restrict__ Wrows,
                                                const float* __restrict__ bias,
                                                float* __restrict__ out, int mode) {
    extern __shared__ float sm[];
    float* aT = sm;
    float* wT = sm + 128 * 68;
    int c0 = blockIdx.x * 64;
    int t0 = blockIdx.y * 64;
    int tid = threadIdx.x;
    for (int idx = tid; idx < 64 * 128; idx += 256) {
        int r = idx >> 7, k = idx & 127;
        aT[k * 68 + r] = A[(t0 + r) * 128 + k];
        wT[k * 68 + r] = Wrows[(c0 + r) * 128 + k];
    }
    __syncthreads();
    int ty = tid >> 4, tx = tid & 15;
    float acc[4][4] = {};
    #pragma unroll 4
    for (int k = 0; k < 128; k++) {
        float4 av = *(const float4*)&aT[k * 68 + 4 * ty];
        float4 bv = *(const float4*)&wT[k * 68 + 4 * tx];
        float a[4] = {av.x, av.y, av.z, av.w};
        float c[4] = {bv.x, bv.y, bv.z, bv.w};
        #pragma unroll
        for (int i = 0; i < 4; i++)
            #pragma unroll
            for (int j = 0; j < 4; j++) acc[i][j] = fmaf(a[i], c[j], acc[i][j]);
    }
    #pragma unroll
    for (int i = 0; i < 4; i++) {
        int token = t0 + 4 * ty + i;
        #pragma unroll
        for (int j = 0; j < 4; j++) {
            int c = c0 + 4 * tx + j;
            float val = acc[i][j] + __ldg(&bias[c]);
            if (mode == 0) {
                if (c < 128) {
                    g_q[token * 128 + c] = val;
                } else if (c < 256) {
                    int d = c - 128;
                    __half hi = __float2half_rn(val);
                    __half lo = __float2half_rn(val - __half2float(hi));
                    g_kh[token * 128 + d] = hi;
                    g_kl[token * 128 + d] = lo;
                } else {
                    int d = c - 256;
                    g_vh[(size_t)d * NTOK + token] = __float2half_rn(val);
                }
            } else if (mode == 1) {
                g_q[token * 128 + c] = 0.5f * val * (1.0f + erff(val * 0.70710678118654752f));
            } else {
                out[token * 128 + c] = val;
            }
        }
    }
}

// ---------------- pairwise distance via tf32 MMA ----------------
__global__ void __launch_bounds__(256) k_dist(const float* __restrict__ x) {
    extern __shared__ float sm[];
    float* xi = sm;              // [128][132], tf32-rounded
    float* xj = sm + 128 * 132;
    int b = blockIdx.z, i0 = blockIdx.y * 128, j0 = blockIdx.x * 128;
    int tid = threadIdx.x;
    for (int fi = tid; fi < 4096; fi += 256) {
        int r = fi >> 5, c4 = (fi & 31) * 4;
        float4 a = *(const float4*)&x[(size_t)(b * SEQ + i0 + r) * 128 + c4];
        float4 bb = *(const float4*)&x[(size_t)(b * SEQ + j0 + r) * 128 + c4];
        a.x = __uint_as_float(f2tf(a.x)); a.y = __uint_as_float(f2tf(a.y));
        a.z = __uint_as_float(f2tf(a.z)); a.w = __uint_as_float(f2tf(a.w));
        bb.x = __uint_as_float(f2tf(bb.x)); bb.y = __uint_as_float(f2tf(bb.y));
        bb.z = __uint_as_float(f2tf(bb.z)); bb.w = __uint_as_float(f2tf(bb.w));
        *(float4*)&xi[r * 132 + c4] = a;
        *(float4*)&xj[r * 132 + c4] = bb;
    }
    __syncthreads();
    int lane = tid & 31, w = tid >> 5;
    int wr = w >> 1, wc = w & 1;
    int g = lane >> 2, t = lane & 3;
    float c[2][8][4] = {};
    #pragma unroll 1
    for (int ks = 0; ks < 16; ks++) {
        uint32_t A[2][4];
        #pragma unroll
        for (int mt = 0; mt < 2; mt++)
            #pragma unroll
            for (int e = 0; e < 4; e++)
                A[mt][e] = __float_as_uint(xi[(32 * wr + 16 * mt + g + 8 * (e & 1)) * 132 + 8 * ks + t + 4 * (e >> 1)]);
        #pragma unroll
        for (int nt = 0; nt < 8; nt++) {
            int row = (64 * wc + 8 * nt + g) * 132 + 8 * ks + t;
            uint32_t b0 = __float_as_uint(xj[row]);
            uint32_t b1 = __float_as_uint(xj[row + 4]);
            mma8(c[0][nt], A[0], b0, b1);
            mma8(c[1][nt], A[1], b0, b1);
        }
    }
    float lsum = 0.f;
    #pragma unroll
    for (int mt = 0; mt < 2; mt++) {
        int ir0 = i0 + 32 * wr + 16 * mt + g;
        float sqi0 = __ldg(&g_sq[b * SEQ + ir0]);
        float sqi1 = __ldg(&g_sq[b * SEQ + ir0 + 8]);
        #pragma unroll
        for (int nt = 0; nt < 8; nt++) {
            int jc = j0 + 64 * wc + 8 * nt + 2 * t;
            float sj0 = __ldg(&g_sq[b * SEQ + jc]);
            float sj1 = __ldg(&g_sq[b * SEQ + jc + 1]);
            float d00 = sqrtf(fmaxf(sqi0 + sj0 - 2.f * c[mt][nt][0], 0.f));
            float d01 = sqrtf(fmaxf(sqi0 + sj1 - 2.f * c[mt][nt][1], 0.f));
            float d10 = sqrtf(fmaxf(sqi1 + sj0 - 2.f * c[mt][nt][2], 0.f));
            float d11 = sqrtf(fmaxf(sqi1 + sj1 - 2.f * c[mt][nt][3], 0.f));
            lsum += d00 + d01 + d10 + d11;
            *(__half2*)&g_dist[(size_t)(b * SEQ + ir0) * SEQ + jc]     = __floats2half2_rn(d00, d01);
            *(__half2*)&g_dist[(size_t)(b * SEQ + ir0 + 8) * SEQ + jc] = __floats2half2_rn(d10, d11);
        }
    }
    #pragma unroll
    for (int o = 16; o; o >>= 1) lsum += __shfl_xor_sync(0xffffffffu, lsum, o);
    __shared__ float rsum[8];
    if (lane == 0) rsum[w] = lsum;
    __syncthreads();
    if (tid == 0) {
        float tot = 0.f;
        #pragma unroll
        for (int i = 0; i < 8; i++) tot += rsum[i];
        atomicAdd(&g_sum_spe, (double)tot);
    }
}

// ---------------- finalize sigmas + spatial LUT ----------------
__global__ void k_finalize() {
    int t = threadIdx.x;
    __shared__ double red[256];
    double local = 0.0;
    for (int idx = t; idx < 64 * 64; idx += 256) {
        int adx = idx >> 6, ady = idx & 63;
        double cx = adx ? 2.0 * (64 - adx) : 64.0;
        double cy = ady ? 2.0 * (64 - ady) : 64.0;
        local += cx * cy * sqrt((double)(adx * adx + ady * ady));
    }
    red[t] = local; __syncthreads();
    for (int s = 128; s; s >>= 1) { if (t < s) red[t] += red[t + s]; __syncthreads(); }
    __shared__ float inv_spa;
    if (t == 0) {
        double sig_spa = red[0] / ((double)SEQ * (double)SEQ);
        inv_spa = (float)(1.0 / (2.0 * sig_spa * sig_spa));
        double sig_spe = g_sum_spe / ((double)BATCH * (double)SEQ * (double)SEQ);
        g_inv2s2_spe = (float)(1.0 / (2.0 * sig_spe * sig_spe));
    }
    __syncthreads();
    float iv = inv_spa;
    for (int idx = t; idx < 64 * 64; idx += 256) {
        int adx = idx >> 6, ady = idx & 63;
        g_spa[idx] = expf(-sqrtf((float)(adx * adx + ady * ady)) * iv);
    }
}

// ---------------- flash attention: fp16 MMA (QK 2-split, PV plain) ----------------
// smem halves: KH [64][136] @0, KL @8704, VH [128][136] @17408, PH [128][72] @34816
// smem floats: WS [64][68] @ byte 71680 ; total 89088+17408 = 106496... see offsets
#define SM_KH 0
#define SM_KL (64 * 136)
#define SM_VH (2 * 64 * 136)
#define SM_PH (2 * 64 * 136 + 128 * 136)
#define SM_HALVES (2 * 64 * 136 + 128 * 136 + 128 * 72)
#define SM_WS_BYTES (SM_HALVES * 2)
#define FLASH_SMEM_BYTES (SM_WS_BYTES + 64 * 68 * 4)
__global__ void __launch_bounds__(256, 1) k_flash() {
    extern __shared__ char smraw[];
    __half* smKH = (__half*)smraw + SM_KH;
    __half* smKL = (__half*)smraw + SM_KL;
    __half* smVH = (__half*)smraw + SM_VH;
    __half* smPH = (__half*)smraw + SM_PH;
    float*  smWS = (float*)(smraw + SM_WS_BYTES);
    int b  = blockIdx.y;
    int i0 = blockIdx.x * 64;
    int tid = threadIdx.x;
    int lane = tid & 31, w = tid >> 5;
    int h = w >> 2, ms = w & 3;
    int g = lane >> 2, t = lane & 3;
    int hb = h * 64;
    int r0loc = 16 * ms + g;
    float inv_spe = g_inv2s2_spe;

    // ---- Q fragments: fp16 hi/lo, m16n8k16 A layout, 4 k-steps ----
    uint32_t qh[4][4], ql[4][4];
    #pragma unroll
    for (int ks = 0; ks < 4; ks++)
        #pragma unroll
        for (int e = 0; e < 4; e++) {
            int row = i0 + r0loc + (e & 1) * 8;
            int col = hb + 16 * ks + 2 * t + (e >> 1) * 8;
            float f0 = g_q[(size_t)(b * SEQ + row) * 128 + col];
            float f1 = g_q[(size_t)(b * SEQ + row) * 128 + col + 1];
            __half2 hi2 = __floats2half2_rn(f0, f1);
            float2 back = __half22float2(hi2);
            __half2 lo2 = __floats2half2_rn(f0 - back.x, f1 - back.y);
            qh[ks][e] = *(uint32_t*)&hi2;
            ql[ks][e] = *(uint32_t*)&lo2;
        }

    float co[8][4] = {};
    float m0 = -1e30f, m1 = -1e30f, l0 = 0.f, l1 = 0.f;
    __half* myP = smPH + hb * 72;
    int gxi0 = (i0 + r0loc) >> 6;        // varies with row; recompute per use
    (void)gxi0;

    for (int jt = 0; jt < 64; jt++) {
        int j0 = jt * 64;
        __syncthreads();
        // ---- fill K hi/lo + V planes (pure copy) ----
        #pragma unroll
        for (int fi = tid; fi < 3072; fi += 256) {
            if (fi < 1024) {
                int r = fi >> 4, c = fi & 15;
                *(uint4*)&smKH[r * 136 + c * 8] =
                    *(const uint4*)&g_kh[(size_t)(b * SEQ + j0 + r) * 128 + c * 8];
            } else if (fi < 2048) {
                int v = fi - 1024, r = v >> 4, c = v & 15;
                *(uint4*)&smKL[r * 136 + c * 8] =
                    *(const uint4*)&g_kl[(size_t)(b * SEQ + j0 + r) * 128 + c * 8];
            } else {
                int v = fi - 2048, d = v >> 3, c = v & 7;
                *(uint4*)&smVH[d * 136 + c * 8] =
                    *(const uint4*)&g_vh[(size_t)d * NTOK + b * SEQ + j0 + c * 8];
            }
        }
        // ---- mask tile: spa * exp(-dist*c) ----
        int jx = j0 >> 6;
        #pragma unroll
        for (int ii = tid; ii < 2048; ii += 256) {
            int i = ii >> 5, c2 = (ii & 31) * 2;
            __half2 d2 = *(const __half2*)&g_dist[(size_t)(b * SEQ + i0 + i) * SEQ + j0 + c2];
            float2 df = __half22float2(d2);
            int gi = i0 + i;
            int adx = abs((gi >> 6) - jx);
            int gyi = gi & 63;
            const float* spaRow = &g_spa[adx * 64];
            float2 wv;
            wv.x = spaRow[abs(gyi - c2)] * __expf(-df.x * inv_spe);
            wv.y = spaRow[abs(gyi - (c2 + 1))] * __expf(-df.y * inv_spe);
            *(float2*)&smWS[i * 68 + c2] = wv;
        }
        __syncthreads();

        // ---- QK^T: fp16 2-split (hh + hl + lh) ----
        float cs[8][4] = {};
        #pragma unroll
        for (int ks = 0; ks < 4; ks++) {
            #pragma unroll
            for (int nt = 0; nt < 8; nt++) {
                int base = (8 * nt + g) * 136 + hb + 16 * ks + 2 * t;
                uint32_t kh0 = *(const uint32_t*)&smKH[base];
                uint32_t kh1 = *(const uint32_t*)&smKH[base + 8];
                uint32_t kl0 = *(const uint32_t*)&smKL[base];
                uint32_t kl1 = *(const uint32_t*)&smKL[base + 8];
                mma16(cs[nt], qh[ks], kh0, kh1);
                mma16(cs[nt], qh[ks], kl0, kl1);
                mma16(cs[nt], ql[ks], kh0, kh1);
            }
        }

        // ---- mask + online softmax ----
        float mloc0 = -1e30f, mloc1 = -1e30f;
        #pragma unroll
        for (int nt = 0; nt < 8; nt++) {
            int col = 8 * nt + 2 * t;
            float2 wa = *(const float2*)&smWS[r0loc * 68 + col];
            float2 wb = *(const float2*)&smWS[(r0loc + 8) * 68 + col];
            cs[nt][0] *= SCALE * wa.x; cs[nt][1] *= SCALE * wa.y;
            cs[nt][2] *= SCALE * wb.x; cs[nt][3] *= SCALE * wb.y;
            mloc0 = fmaxf(mloc0, fmaxf(cs[nt][0], cs[nt][1]));
            mloc1 = fmaxf(mloc1, fmaxf(cs[nt][2], cs[nt][3]));
        }
        #pragma unroll
        for (int o = 1; o <= 2; o <<= 1) {
            mloc0 = fmaxf(mloc0, __shfl_xor_sync(0xffffffffu, mloc0, o));
            mloc1 = fmaxf(mloc1, __shfl_xor_sync(0xffffffffu, mloc1, o));
        }
        float mn0 = fmaxf(m0, mloc0), mn1 = fmaxf(m1, mloc1);
        float corr0 = __expf(m0 - mn0), corr1 = __expf(m1 - mn1);
        m0 = mn0; m1 = mn1;
        float rs0 = 0.f, rs1 = 0.f;
        #pragma unroll
        for (int nt = 0; nt < 8; nt++) {
            float p0 = __expf(cs[nt][0] - mn0), p1 = __expf(cs[nt][1] - mn0);
            float p2 = __expf(cs[nt][2] - mn1), p3 = __expf(cs[nt][3] - mn1);
            rs0 += p0 + p1; rs1 += p2 + p3;
            int col = 8 * nt + 2 * t;
            *(__half2*)&myP[r0loc * 72 + col]       = __floats2half2_rn(p0, p1);
            *(__half2*)&myP[(r0loc + 8) * 72 + col] = __floats2half2_rn(p2, p3);
        }
        #pragma unroll
        for (int o = 1; o <= 2; o <<= 1) {
            rs0 += __shfl_xor_sync(0xffffffffu, rs0, o);
            rs1 += __shfl_xor_sync(0xffffffffu, rs1, o);
        }
        l0 = l0 * corr0 + rs0;
        l1 = l1 * corr1 + rs1;
        #pragma unroll
        for (int nt = 0; nt < 8; nt++) {
            co[nt][0] *= corr0; co[nt][1] *= corr0;
            co[nt][2] *= corr1; co[nt][3] *= corr1;
        }
        __syncwarp();

        // ---- PV: plain fp16 ----
        #pragma unroll
        for (int ks = 0; ks < 4; ks++) {
            uint32_t pa[4];
            pa[0] = *(const uint32_t*)&myP[r0loc * 72 + 16 * ks + 2 * t];
            pa[1] = *(const uint32_t*)&myP[(r0loc + 8) * 72 + 16 * ks + 2 * t];
            pa[2] = *(const uint32_t*)&myP[r0loc * 72 + 16 * ks + 2 * t + 8];
            pa[3] = *(const uint32_t*)&myP[(r0loc + 8) * 72 + 16 * ks + 2 * t + 8];
            #pragma unroll
            for (int nt = 0; nt < 8; nt++) {
                int base = (hb + 8 * nt + g) * 136 + 16 * ks + 2 * t;
                uint32_t b0 = *(const uint32_t*)&smVH[base];
                uint32_t b1 = *(const uint32_t*)&smVH[base + 8];
                mma16(co[nt], pa, b0, b1);
            }
        }
    }

    // ---- epilogue ----
    float li0 = 1.f / l0, li1 = 1.f / l1;
    #pragma unroll
    for (int nt = 0; nt < 8; nt++) {
        int col = hb + 8 * nt + 2 * t;
        int row0 = b * SEQ + i0 + r0loc;
        float2 o0 = {co[nt][0] * li0, co[nt][1] * li0};
        float2 o1 = {co[nt][2] * li1, co[nt][3] * li1};
        *(float2*)&g_attn[(size_t)row0 * 128 + col] = o0;
        *(float2*)&g_attn[(size_t)(row0 + 8) * 128 + col] = o1;
    }
}

// ---------------- launch ----------------
extern "C" void kernel_launch(void* const* d_in, const int* in_sizes, int n_in,
                              void* d_out, int out_size) {
    const float* x      = (const float*)d_in[0];
    const float* v_qkv  = (const float*)d_in[1];
    const float* g_qkv_ = (const float*)d_in[2];
    const float* b_qkv  = (const float*)d_in[3];
    const float* v_ff1  = (const float*)d_in[4];
    const float* g_ff1  = (const float*)d_in[5];
    const float* b_ff1  = (const float*)d_in[6];
    const float* v_ff2  = (const float*)d_in[7];
    const float* g_ff2  = (const float*)d_in[8];
    const float* b_ff2  = (const float*)d_in[9];
    float* out = (float*)d_out;

    const int GEMM_SMEM = 2 * 128 * 68 * 4;
    const int DIST_SMEM = 2 * 128 * 132 * 4;
    cudaFuncSetAttribute(k_gemm64, cudaFuncAttributeMaxDynamicSharedMemorySize, GEMM_SMEM);
    cudaFuncSetAttribute(k_dist,   cudaFuncAttributeMaxDynamicSharedMemorySize, DIST_SMEM);
    cudaFuncSetAttribute(k_flash,  cudaFuncAttributeMaxDynamicSharedMemorySize, FLASH_SMEM_BYTES);

    float* Wdev = nullptr;     cudaGetSymbolAddress((void**)&Wdev, g_W);
    float* attn_dev = nullptr; cudaGetSymbolAddress((void**)&attn_dev, g_attn);
    float* h1_dev = nullptr;   cudaGetSymbolAddress((void**)&h1_dev, g_q);

    k_init<<<1, 1>>>();
    k_weights<<<640, 128>>>(v_qkv, g_qkv_, v_ff1, g_ff1, v_ff2, g_ff2);
    k_sq<<<NTOK / 8, 256>>>(x);
    k_gemm64<<<dim3(6, NTOK / 64), 256, GEMM_SMEM>>>(x, Wdev, b_qkv, nullptr, 0);
    k_dist<<<dim3(32, 32, BATCH), 256, DIST_SMEM>>>(x);
    k_finalize<<<1, 256>>>();
    k_flash<<<dim3(64, BATCH), 256, FLASH_SMEM_BYTES>>>();
    k_gemm64<<<dim3(2, NTOK / 64), 256, GEMM_SMEM>>>(attn_dev, Wdev + 384 * 128, b_ff1, nullptr, 1);
    k_gemm64<<<dim3(2, NTOK / 64), 256, GEMM_SMEM>>>(h1_dev, Wdev + 512 * 128, b_ff2, out, 2);
}

// round 7
// speedup vs baseline: 2.0422x; 1.0338x over previous
#include <cuda_runtime.h>
#include <cuda_fp16.h>
#include <math.h>
#include <stdint.h>

#define BATCH 2
#define SEQ   4096
#define DIM   128
#define NTOK  (BATCH * SEQ)
#define SCALE 0.125f   // 64^-0.5

// ---------------- device scratch ----------------
__device__ float  g_W[640 * 128];
__device__ float  g_q[NTOK * DIM];            // reused as h1 after flash
__device__ __half g_kh[NTOK * DIM];           // K hi plane [tok][d]
__device__ __half g_kl[NTOK * DIM];           // K lo plane
__device__ __half g_vh[(size_t)DIM * NTOK];   // V fp16, transposed [d][tok]
__device__ float  g_sq[NTOK];
__device__ __half g_dist[(size_t)BATCH * SEQ * SEQ]; // fp16 distances
__device__ double g_sum_spe;
__device__ float  g_inv2s2_spe;
__device__ float  g_spa[64 * 64];
__device__ float  g_attn[NTOK * DIM];

// ---------------- helpers ----------------
__device__ __forceinline__ uint32_t f2tf(float f) {
    uint32_t r; asm("cvt.rna.tf32.f32 %0, %1;" : "=r"(r) : "f"(f)); return r;
}
__device__ __forceinline__ void mma8(float* c, const uint32_t* a, uint32_t b0, uint32_t b1) {
    asm volatile("mma.sync.aligned.m16n8k8.row.col.f32.tf32.tf32.f32 "
                 "{%0,%1,%2,%3},{%4,%5,%6,%7},{%8,%9},{%0,%1,%2,%3};"
                 : "+f"(c[0]), "+f"(c[1]), "+f"(c[2]), "+f"(c[3])
                 : "r"(a[0]), "r"(a[1]), "r"(a[2]), "r"(a[3]), "r"(b0), "r"(b1));
}
__device__ __forceinline__ void mma16(float* c, const uint32_t* a, uint32_t b0, uint32_t b1) {
    asm volatile("mma.sync.aligned.m16n8k16.row.col.f32.f16.f16.f32 "
                 "{%0,%1,%2,%3},{%4,%5,%6,%7},{%8,%9},{%0,%1,%2,%3};"
                 : "+f"(c[0]), "+f"(c[1]), "+f"(c[2]), "+f"(c[3])
                 : "r"(a[0]), "r"(a[1]), "r"(a[2]), "r"(a[3]), "r"(b0), "r"(b1));
}

// ---------------- init ----------------
__global__ void k_init() { g_sum_spe = 0.0; }

// ---------------- weight norm ----------------
__global__ void k_weights(const float* __restrict__ vq, const float* __restrict__ gq,
                          const float* __restrict__ v1, const float* __restrict__ g1,
                          const float* __restrict__ v2, const float* __restrict__ g2) {
    int r = blockIdx.x, t = threadIdx.x;
    const float* v; float g;
    if (r < 384)      { v = vq + r * 128;        g = gq[r]; }
    else if (r < 512) { v = v1 + (r - 384) * 128; g = g1[r - 384]; }
    else              { v = v2 + (r - 512) * 128; g = g2[r - 512]; }
    float val = v[t];
    float ss = val * val;
    #pragma unroll
    for (int o = 16; o; o >>= 1) ss += __shfl_xor_sync(0xffffffffu, ss, o);
    __shared__ float ws[4];
    if ((t & 31) == 0) ws[t >> 5] = ss;
    __syncthreads();
    float tot = ws[0] + ws[1] + ws[2] + ws[3];
    g_W[r * 128 + t] = val * (g / sqrtf(tot));
}

// ---------------- per-token ||x||^2 ----------------
__global__ void k_sq(const float* __restrict__ x) {
    int token = blockIdx.x * 8 + (threadIdx.x >> 5);
    int lane  = threadIdx.x & 31;
    const float4* xp = (const float4*)(x + token * 128);
    float4 a = xp[lane];
    float ss = a.x * a.x + a.y * a.y + a.z * a.z + a.w * a.w;
    #pragma unroll
    for (int o = 16; o; o >>= 1) ss += __shfl_xor_sync(0xffffffffu, ss, o);
    if (lane == 0) g_sq[token] = ss;
}

// ---------------- tiled projection GEMM (scalar fp32, exact) ----------------
__global__ void __launch_bounds__(256) k_gemm64(const float* __restrict__ A,
                                                const float* __restrict__ Wrows,
                                                const float* __restrict__ bias,
                                                float* __restrict__ out, int mode) {
    extern __shared__ float sm[];
    float* aT = sm;
    float* wT = sm + 128 * 68;
    int c0 = blockIdx.x * 64;
    int t0 = blockIdx.y * 64;
    int tid = threadIdx.x;
    for (int idx = tid; idx < 64 * 128; idx += 256) {
        int r = idx >> 7, k = idx & 127;
        aT[k * 68 + r] = A[(t0 + r) * 128 + k];
        wT[k * 68 + r] = Wrows[(c0 + r) * 128 + k];
    }
    __syncthreads();
    int ty = tid >> 4, tx = tid & 15;
    float acc[4][4] = {};
    #pragma unroll 4
    for (int k = 0; k < 128; k++) {
        float4 av = *(const float4*)&aT[k * 68 + 4 * ty];
        float4 bv = *(const float4*)&wT[k * 68 + 4 * tx];
        float a[4] = {av.x, av.y, av.z, av.w};
        float c[4] = {bv.x, bv.y, bv.z, bv.w};
        #pragma unroll
        for (int i = 0; i < 4; i++)
            #pragma unroll
            for (int j = 0; j < 4; j++) acc[i][j] = fmaf(a[i], c[j], acc[i][j]);
    }
    #pragma unroll
    for (int i = 0; i < 4; i++) {
        int token = t0 + 4 * ty + i;
        #pragma unroll
        for (int j = 0; j < 4; j++) {
            int c = c0 + 4 * tx + j;
            float val = acc[i][j] + __ldg(&bias[c]);
            if (mode == 0) {
                if (c < 128) {
                    g_q[token * 128 + c] = val;
                } else if (c < 256) {
                    int d = c - 128;
                    __half hi = __float2half_rn(val);
                    __half lo = __float2half_rn(val - __half2float(hi));
                    g_kh[token * 128 + d] = hi;
                    g_kl[token * 128 + d] = lo;
                } else {
                    int d = c - 256;
                    g_vh[(size_t)d * NTOK + token] = __float2half_rn(val);
                }
            } else if (mode == 1) {
                g_q[token * 128 + c] = 0.5f * val * (1.0f + erff(val * 0.70710678118654752f));
            } else {
                out[token * 128 + c] = val;
            }
        }
    }
}

// ---------------- pairwise distance via tf32 MMA ----------------
__global__ void __launch_bounds__(256) k_dist(const float* __restrict__ x) {
    extern __shared__ float sm[];
    float* xi = sm;              // [128][132], tf32-rounded
    float* xj = sm + 128 * 132;
    int b = blockIdx.z, i0 = blockIdx.y * 128, j0 = blockIdx.x * 128;
    int tid = threadIdx.x;
    for (int fi = tid; fi < 4096; fi += 256) {
        int r = fi >> 5, c4 = (fi & 31) * 4;
        float4 a = *(const float4*)&x[(size_t)(b * SEQ + i0 + r) * 128 + c4];
        float4 bb = *(const float4*)&x[(size_t)(b * SEQ + j0 + r) * 128 + c4];
        a.x = __uint_as_float(f2tf(a.x)); a.y = __uint_as_float(f2tf(a.y));
        a.z = __uint_as_float(f2tf(a.z)); a.w = __uint_as_float(f2tf(a.w));
        bb.x = __uint_as_float(f2tf(bb.x)); bb.y = __uint_as_float(f2tf(bb.y));
        bb.z = __uint_as_float(f2tf(bb.z)); bb.w = __uint_as_float(f2tf(bb.w));
        *(float4*)&xi[r * 132 + c4] = a;
        *(float4*)&xj[r * 132 + c4] = bb;
    }
    __syncthreads();
    int lane = tid & 31, w = tid >> 5;
    int wr = w >> 1, wc = w & 1;
    int g = lane >> 2, t = lane & 3;
    float c[2][8][4] = {};
    #pragma unroll 1
    for (int ks = 0; ks < 16; ks++) {
        uint32_t A[2][4];
        #pragma unroll
        for (int mt = 0; mt < 2; mt++)
            #pragma unroll
            for (int e = 0; e < 4; e++)
                A[mt][e] = __float_as_uint(xi[(32 * wr + 16 * mt + g + 8 * (e & 1)) * 132 + 8 * ks + t + 4 * (e >> 1)]);
        #pragma unroll
        for (int nt = 0; nt < 8; nt++) {
            int row = (64 * wc + 8 * nt + g) * 132 + 8 * ks + t;
            uint32_t b0 = __float_as_uint(xj[row]);
            uint32_t b1 = __float_as_uint(xj[row + 4]);
            mma8(c[0][nt], A[0], b0, b1);
            mma8(c[1][nt], A[1], b0, b1);
        }
    }
    float lsum = 0.f;
    #pragma unroll
    for (int mt = 0; mt < 2; mt++) {
        int ir0 = i0 + 32 * wr + 16 * mt + g;
        float sqi0 = __ldg(&g_sq[b * SEQ + ir0]);
        float sqi1 = __ldg(&g_sq[b * SEQ + ir0 + 8]);
        #pragma unroll
        for (int nt = 0; nt < 8; nt++) {
            int jc = j0 + 64 * wc + 8 * nt + 2 * t;
            float sj0 = __ldg(&g_sq[b * SEQ + jc]);
            float sj1 = __ldg(&g_sq[b * SEQ + jc + 1]);
            float d00 = sqrtf(fmaxf(sqi0 + sj0 - 2.f * c[mt][nt][0], 0.f));
            float d01 = sqrtf(fmaxf(sqi0 + sj1 - 2.f * c[mt][nt][1], 0.f));
            float d10 = sqrtf(fmaxf(sqi1 + sj0 - 2.f * c[mt][nt][2], 0.f));
            float d11 = sqrtf(fmaxf(sqi1 + sj1 - 2.f * c[mt][nt][3], 0.f));
            lsum += d00 + d01 + d10 + d11;
            *(__half2*)&g_dist[(size_t)(b * SEQ + ir0) * SEQ + jc]     = __floats2half2_rn(d00, d01);
            *(__half2*)&g_dist[(size_t)(b * SEQ + ir0 + 8) * SEQ + jc] = __floats2half2_rn(d10, d11);
        }
    }
    #pragma unroll
    for (int o = 16; o; o >>= 1) lsum += __shfl_xor_sync(0xffffffffu, lsum, o);
    __shared__ float rsum[8];
    if (lane == 0) rsum[w] = lsum;
    __syncthreads();
    if (tid == 0) {
        float tot = 0.f;
        #pragma unroll
        for (int i = 0; i < 8; i++) tot += rsum[i];
        atomicAdd(&g_sum_spe, (double)tot);
    }
}

// ---------------- finalize sigmas + spatial LUT ----------------
__global__ void k_finalize() {
    int t = threadIdx.x;
    __shared__ double red[256];
    double local = 0.0;
    for (int idx = t; idx < 64 * 64; idx += 256) {
        int adx = idx >> 6, ady = idx & 63;
        double cx = adx ? 2.0 * (64 - adx) : 64.0;
        double cy = ady ? 2.0 * (64 - ady) : 64.0;
        local += cx * cy * sqrt((double)(adx * adx + ady * ady));
    }
    red[t] = local; __syncthreads();
    for (int s = 128; s; s >>= 1) { if (t < s) red[t] += red[t + s]; __syncthreads(); }
    __shared__ float inv_spa;
    if (t == 0) {
        double sig_spa = red[0] / ((double)SEQ * (double)SEQ);
        inv_spa = (float)(1.0 / (2.0 * sig_spa * sig_spa));
        double sig_spe = g_sum_spe / ((double)BATCH * (double)SEQ * (double)SEQ);
        g_inv2s2_spe = (float)(1.0 / (2.0 * sig_spe * sig_spe));
    }
    __syncthreads();
    float iv = inv_spa;
    for (int idx = t; idx < 64 * 64; idx += 256) {
        int adx = idx >> 6, ady = idx & 63;
        g_spa[idx] = expf(-sqrtf((float)(adx * adx + ady * ady)) * iv);
    }
}

// ---------------- flash attention: fp16 MMA, P-in-registers, double-buffered ----------------
// smem: 2 KV buffers (KH[64][136], KL[64][136], V[128][136] halves = 34816 halves each)
//       2 WS buffers (64x68 floats) at byte 139264
#define KVB 34816
#define WSF 4352
#define WS_BYTE_OFF (2 * KVB * 2)
#define FLASH_SMEM_BYTES (WS_BYTE_OFF + 2 * WSF * 4)   // 174080
__global__ void __launch_bounds__(256, 1) k_flash() {
    extern __shared__ char smraw[];
    __half* smKV = (__half*)smraw;
    float*  smWS = (float*)(smraw + WS_BYTE_OFF);
    int b  = blockIdx.y;
    int i0 = blockIdx.x * 64;
    int tid = threadIdx.x;
    int lane = tid & 31, w = tid >> 5;
    int h = w >> 2, ms = w & 3;
    int g = lane >> 2, t = lane & 3;
    int hb = h * 64;
    int r0loc = 16 * ms + g;
    float inv_spe = g_inv2s2_spe;

    // ---- Q fragments: fp16 hi/lo ----
    uint32_t qh[4][4], ql[4][4];
    #pragma unroll
    for (int ks = 0; ks < 4; ks++)
        #pragma unroll
        for (int e = 0; e < 4; e++) {
            int row = i0 + r0loc + (e & 1) * 8;
            int col = hb + 16 * ks + 2 * t + (e >> 1) * 8;
            float f0 = g_q[(size_t)(b * SEQ + row) * 128 + col];
            float f1 = g_q[(size_t)(b * SEQ + row) * 128 + col + 1];
            __half2 hi2 = __floats2half2_rn(f0, f1);
            float2 back = __half22float2(hi2);
            __half2 lo2 = __floats2half2_rn(f0 - back.x, f1 - back.y);
            qh[ks][e] = *(uint32_t*)&hi2;
            ql[ks][e] = *(uint32_t*)&lo2;
        }

    auto fill_kv = [&](int pbuf, int j0) {
        __half* KH = smKV + pbuf * KVB;
        __half* KL = KH + 64 * 136;
        __half* VV = KH + 2 * 64 * 136;
        #pragma unroll
        for (int fi = tid; fi < 3072; fi += 256) {
            if (fi < 1024) {
                int r = fi >> 4, c = fi & 15;
                *(uint4*)&KH[r * 136 + c * 8] =
                    *(const uint4*)&g_kh[(size_t)(b * SEQ + j0 + r) * 128 + c * 8];
            } else if (fi < 2048) {
                int v = fi - 1024, r = v >> 4, c = v & 15;
                *(uint4*)&KL[r * 136 + c * 8] =
                    *(const uint4*)&g_kl[(size_t)(b * SEQ + j0 + r) * 128 + c * 8];
            } else {
                int v = fi - 2048, d = v >> 3, c = v & 7;
                *(uint4*)&VV[d * 136 + c * 8] =
                    *(const uint4*)&g_vh[(size_t)d * NTOK + b * SEQ + j0 + c * 8];
            }
        }
    };
    auto fill_ws = [&](int pbuf, int j0) {
        float* WS = smWS + pbuf * WSF;
        int jx = j0 >> 6;
        #pragma unroll
        for (int ii = tid; ii < 2048; ii += 256) {
            int i = ii >> 5, c2 = (ii & 31) * 2;
            __half2 d2 = *(const __half2*)&g_dist[(size_t)(b * SEQ + i0 + i) * SEQ + j0 + c2];
            float2 df = __half22float2(d2);
            int gi = i0 + i;
            int adx = abs((gi >> 6) - jx);
            int gyi = gi & 63;
            const float* spaRow = &g_spa[adx * 64];
            float2 wv;
            wv.x = spaRow[abs(gyi - c2)] * __expf(-df.x * inv_spe);
            wv.y = spaRow[abs(gyi - (c2 + 1))] * __expf(-df.y * inv_spe);
            *(float2*)&WS[i * 68 + c2] = wv;
        }
    };

    float co[8][4] = {};
    float m0 = -1e30f, m1 = -1e30f, l0 = 0.f, l1 = 0.f;

    fill_kv(0, 0);
    fill_ws(0, 0);
    __syncthreads();

    for (int jt = 0; jt < 64; jt++) {
        int p = jt & 1;
        if (jt < 63) {                // prefetch next tile into alt buffers
            fill_kv(1 - p, (jt + 1) * 64);
            fill_ws(1 - p, (jt + 1) * 64);
        }
        const __half* KH = smKV + p * KVB;
        const __half* KL = KH + 64 * 136;
        const __half* VV = KH + 2 * 64 * 136;
        const float*  WS = smWS + p * WSF;

        // ---- QK^T: fp16 2-split (hh + hl + lh) ----
        float cs[8][4] = {};
        #pragma unroll
        for (int ks = 0; ks < 4; ks++) {
            #pragma unroll
            for (int nt = 0; nt < 8; nt++) {
                int base = (8 * nt + g) * 136 + hb + 16 * ks + 2 * t;
                uint32_t kh0 = *(const uint32_t*)&KH[base];
                uint32_t kh1 = *(const uint32_t*)&KH[base + 8];
                uint32_t kl0 = *(const uint32_t*)&KL[base];
                uint32_t kl1 = *(const uint32_t*)&KL[base + 8];
                mma16(cs[nt], qh[ks], kh0, kh1);
                mma16(cs[nt], qh[ks], kl0, kl1);
                mma16(cs[nt], ql[ks], kh0, kh1);
            }
        }

        // ---- mask + online softmax (P stays in registers) ----
        float mloc0 = -1e30f, mloc1 = -1e30f;
        #pragma unroll
        for (int nt = 0; nt < 8; nt++) {
            int col = 8 * nt + 2 * t;
            float2 wa = *(const float2*)&WS[r0loc * 68 + col];
            float2 wb = *(const float2*)&WS[(r0loc + 8) * 68 + col];
            cs[nt][0] *= SCALE * wa.x; cs[nt][1] *= SCALE * wa.y;
            cs[nt][2] *= SCALE * wb.x; cs[nt][3] *= SCALE * wb.y;
            mloc0 = fmaxf(mloc0, fmaxf(cs[nt][0], cs[nt][1]));
            mloc1 = fmaxf(mloc1, fmaxf(cs[nt][2], cs[nt][3]));
        }
        #pragma unroll
        for (int o = 1; o <= 2; o <<= 1) {
            mloc0 = fmaxf(mloc0, __shfl_xor_sync(0xffffffffu, mloc0, o));
            mloc1 = fmaxf(mloc1, __shfl_xor_sync(0xffffffffu, mloc1, o));
        }
        float mn0 = fmaxf(m0, mloc0), mn1 = fmaxf(m1, mloc1);
        float corr0 = __expf(m0 - mn0), corr1 = __expf(m1 - mn1);
        m0 = mn0; m1 = mn1;
        float rs0 = 0.f, rs1 = 0.f;
        uint32_t plo[8], phi[8];    // row r0loc / r0loc+8 P fragments (half2)
        #pragma unroll
        for (int nt = 0; nt < 8; nt++) {
            float p0 = __expf(cs[nt][0] - mn0), p1 = __expf(cs[nt][1] - mn0);
            float p2 = __expf(cs[nt][2] - mn1), p3 = __expf(cs[nt][3] - mn1);
            rs0 += p0 + p1; rs1 += p2 + p3;
            __half2 a = __floats2half2_rn(p0, p1);
            __half2 bb = __floats2half2_rn(p2, p3);
            plo[nt] = *(uint32_t*)&a;
            phi[nt] = *(uint32_t*)&bb;
        }
        #pragma unroll
        for (int o = 1; o <= 2; o <<= 1) {
            rs0 += __shfl_xor_sync(0xffffffffu, rs0, o);
            rs1 += __shfl_xor_sync(0xffffffffu, rs1, o);
        }
        l0 = l0 * corr0 + rs0;
        l1 = l1 * corr1 + rs1;
        #pragma unroll
        for (int nt = 0; nt < 8; nt++) {
            co[nt][0] *= corr0; co[nt][1] *= corr0;
            co[nt][2] *= corr1; co[nt][3] *= corr1;
        }

        // ---- PV: plain fp16, A fragments direct from registers ----
        #pragma unroll
        for (int ks = 0; ks < 4; ks++) {
            uint32_t pa[4] = {plo[2 * ks], phi[2 * ks], plo[2 * ks + 1], phi[2 * ks + 1]};
            #pragma unroll
            for (int nt = 0; nt < 8; nt++) {
                int base = (hb + 8 * nt + g) * 136 + 16 * ks + 2 * t;
                uint32_t b0 = *(const uint32_t*)&VV[base];
                uint32_t b1 = *(const uint32_t*)&VV[base + 8];
                mma16(co[nt], pa, b0, b1);
            }
        }
        __syncthreads();   // prefetch fills done; everyone done reading buf p
    }

    // ---- epilogue ----
    float li0 = 1.f / l0, li1 = 1.f / l1;
    #pragma unroll
    for (int nt = 0; nt < 8; nt++) {
        int col = hb + 8 * nt + 2 * t;
        int row0 = b * SEQ + i0 + r0loc;
        float2 o0 = {co[nt][0] * li0, co[nt][1] * li0};
        float2 o1 = {co[nt][2] * li1, co[nt][3] * li1};
        *(float2*)&g_attn[(size_t)row0 * 128 + col] = o0;
        *(float2*)&g_attn[(size_t)(row0 + 8) * 128 + col] = o1;
    }
}

// ---------------- launch ----------------
extern "C" void kernel_launch(void* const* d_in, const int* in_sizes, int n_in,
                              void* d_out, int out_size) {
    const float* x      = (const float*)d_in[0];
    const float* v_qkv  = (const float*)d_in[1];
    const float* g_qkv_ = (const float*)d_in[2];
    const float* b_qkv  = (const float*)d_in[3];
    const float* v_ff1  = (const float*)d_in[4];
    const float* g_ff1  = (const float*)d_in[5];
    const float* b_ff1  = (const float*)d_in[6];
    const float* v_ff2  = (const float*)d_in[7];
    const float* g_ff2  = (const float*)d_in[8];
    const float* b_ff2  = (const float*)d_in[9];
    float* out = (float*)d_out;

    const int GEMM_SMEM = 2 * 128 * 68 * 4;
    const int DIST_SMEM = 2 * 128 * 132 * 4;
    cudaFuncSetAttribute(k_gemm64, cudaFuncAttributeMaxDynamicSharedMemorySize, GEMM_SMEM);
    cudaFuncSetAttribute(k_dist,   cudaFuncAttributeMaxDynamicSharedMemorySize, DIST_SMEM);
    cudaFuncSetAttribute(k_flash,  cudaFuncAttributeMaxDynamicSharedMemorySize, FLASH_SMEM_BYTES);

    float* Wdev = nullptr;     cudaGetSymbolAddress((void**)&Wdev, g_W);
    float* attn_dev = nullptr; cudaGetSymbolAddress((void**)&attn_dev, g_attn);
    float* h1_dev = nullptr;   cudaGetSymbolAddress((void**)&h1_dev, g_q);

    k_init<<<1, 1>>>();
    k_weights<<<640, 128>>>(v_qkv, g_qkv_, v_ff1, g_ff1, v_ff2, g_ff2);
    k_sq<<<NTOK / 8, 256>>>(x);
    k_gemm64<<<dim3(6, NTOK / 64), 256, GEMM_SMEM>>>(x, Wdev, b_qkv, nullptr, 0);
    k_dist<<<dim3(32, 32, BATCH), 256, DIST_SMEM>>>(x);
    k_finalize<<<1, 256>>>();
    k_flash<<<dim3(64, BATCH), 256, FLASH_SMEM_BYTES>>>();
    k_gemm64<<<dim3(2, NTOK / 64), 256, GEMM_SMEM>>>(attn_dev, Wdev + 384 * 128, b_ff1, nullptr, 1);
    k_gemm64<<<dim3(2, NTOK / 64), 256, GEMM_SMEM>>>(h1_dev, Wdev + 512 * 128, b_ff2, out, 2);
}